// round 2
// baseline (speedup 1.0000x reference)
#include <cuda_runtime.h>
#include <cstdint>

// ---------------------------------------------------------------------------
// Problem constants
// ---------------------------------------------------------------------------
#define K_TOTAL   98304      // F = 3*256*128
#define KSPLITS   74
#define TOT_STEPS 3072       // K_TOTAL / 32
#define M_ROWS    128        // B*N = 32*4
#define D_DIM     512
#define N_TILE    256        // N per CTA (2 halves)

#define D_ELEMS   (32*32*3*512)        // 1572864
#define W_ELEMS   (32*32*3*3)          // 9216
#define L_ELEMS   (32*32*3)            // 3072
#define W_OFF     D_ELEMS
#define L_OFF     (D_ELEMS + W_ELEMS)

// smem layout: raw fp32 double-buffer then f16 double-buffer
#define RAWA_BYTES 16384     // 128 m x 32 k fp32
#define RAWB_BYTES 32768     // 32 k x 256 n fp32
#define RAW_STAGE  (RAWA_BYTES + RAWB_BYTES)       // 49152
#define F16A_BYTES 16384     // 128 rows x (32 hi + 32 lo) f16 = 128B rows
#define F16B_BYTES 32768     // 32 rows x (256 hi + 256 lo) f16 = 1KB rows
#define F16_STAGE  (F16A_BYTES + F16B_BYTES)       // 49152
#define SMEM_F16_BASE (2 * RAW_STAGE)              // 98304
#define SMEM_TOTAL (2 * RAW_STAGE + 2 * F16_STAGE) // 196608

// ---------------------------------------------------------------------------
// Scratch (static __device__: no allocation allowed)
// ---------------------------------------------------------------------------
__device__ float g_partial[(size_t)KSPLITS * M_ROWS * D_DIM];   // ~18.5 MB
__device__ float g_e[M_ROWS * D_DIM];                           // 256 KB

// ---------------------------------------------------------------------------
// PTX helpers (sm_80-era: portable to sm_100 base target)
// ---------------------------------------------------------------------------
__device__ __forceinline__ uint32_t smem_u32(const void* p) {
    uint32_t a;
    asm("{ .reg .u64 t; cvta.to.shared.u64 t, %1; cvt.u32.u64 %0, t; }"
        : "=r"(a) : "l"(p));
    return a;
}

__device__ __forceinline__ void cp16(uint32_t dst, const void* src) {
    asm volatile("cp.async.cg.shared.global [%0], [%1], 16;"
                 :: "r"(dst), "l"(src) : "memory");
}
__device__ __forceinline__ void cp_commit() {
    asm volatile("cp.async.commit_group;" ::: "memory");
}
__device__ __forceinline__ void cp_wait1() {
    asm volatile("cp.async.wait_group 1;" ::: "memory");
}

__device__ __forceinline__ void ldsm_x4(uint32_t* r, uint32_t a) {
    asm volatile("ldmatrix.sync.aligned.m8n8.x4.shared.b16 {%0,%1,%2,%3}, [%4];"
                 : "=r"(r[0]), "=r"(r[1]), "=r"(r[2]), "=r"(r[3]) : "r"(a));
}
__device__ __forceinline__ void ldsm_x4_t(uint32_t* r, uint32_t a) {
    asm volatile("ldmatrix.sync.aligned.m8n8.x4.trans.shared.b16 {%0,%1,%2,%3}, [%4];"
                 : "=r"(r[0]), "=r"(r[1]), "=r"(r[2]), "=r"(r[3]) : "r"(a));
}

__device__ __forceinline__ void mma16816(float* c, const uint32_t* a,
                                         const uint32_t* b) {
    asm volatile(
        "mma.sync.aligned.m16n8k16.row.col.f32.f16.f16.f32 "
        "{%0,%1,%2,%3}, {%4,%5,%6,%7}, {%8,%9}, {%0,%1,%2,%3};"
        : "+f"(c[0]), "+f"(c[1]), "+f"(c[2]), "+f"(c[3])
        : "r"(a[0]), "r"(a[1]), "r"(a[2]), "r"(a[3]), "r"(b[0]), "r"(b[1]));
}

// fp32 pair -> f16x2 hi + f16x2 lo (residual). Exact split: lo = rn16(f - hi).
__device__ __forceinline__ void hsplit2(float f0, float f1,
                                        uint32_t& hi, uint32_t& lo) {
    uint32_t h;
    asm("cvt.rn.f16x2.f32 %0, %1, %2;" : "=r"(h) : "f"(f1), "f"(f0));
    float h0, h1;
    asm("{.reg .f16 x,y; mov.b32 {x,y}, %2; cvt.f32.f16 %0, x; cvt.f32.f16 %1, y;}"
        : "=f"(h0), "=f"(h1) : "r"(h));
    float r0 = f0 - h0;
    float r1 = f1 - h1;
    asm("cvt.rn.f16x2.f32 %0, %1, %2;" : "=r"(lo) : "f"(r1), "f"(r0));
    hi = h;
}

// ---------------------------------------------------------------------------
// Kernel 1: split-K fp16 3-term GEMM -> partial sums
// grid = 148 CTAs: blockIdx.x = kidx*2 + nhalf ; 512 threads
// ---------------------------------------------------------------------------
__global__ __launch_bounds__(512, 1)
void gemm_split_kernel(const float* __restrict__ x, const float* __restrict__ W) {
    extern __shared__ char smem[];
    const uint32_t sb = smem_u32(smem);
    const int tid  = threadIdx.x;
    const int wid  = tid >> 5;
    const int lane = tid & 31;

    const int nhalf = blockIdx.x & 1;
    const int kidx  = blockIdx.x >> 1;
    const int ncol0 = nhalf * N_TILE;
    // distribute 3072 32-wide K-steps over 74 splits: 38 CTAs get 42, rest 41
    const int nsteps = 41 + (kidx < 38 ? 1 : 0);
    const int step0  = kidx * 41 + (kidx < 38 ? kidx : 38);

    // ---- cp.async issue for one stage ----
    // A raw: [m 0..127][k 0..31] fp32, 128B rows, 16B-chunk swizzle by (m&7)
    // B raw: [k 0..31][n 0..255] fp32, 1KB rows, chunk swizzle by (k&7)
    const int am  = tid & 127;
    const int ac0 = (tid >> 7) * 2;
    const int bk  = tid >> 4;
    const int bc0 = tid & 15;
    const float* srcA0 = x + (size_t)am * K_TOTAL + (size_t)step0 * 32;
    const float* srcB0 = W + ((size_t)step0 * 32 + bk) * D_DIM + ncol0;

    auto issue = [&](int s, int buf) {
        const uint32_t ra = sb + buf * RAW_STAGE;
        const uint32_t rb = ra + RAWA_BYTES;
        const float* sA = srcA0 + (size_t)s * 32;
        #pragma unroll
        for (int i = 0; i < 2; i++) {
            int cb = ac0 + i;
            cp16(ra + am * 128 + ((cb ^ (am & 7)) << 4), sA + cb * 4);
        }
        const float* sB = srcB0 + (size_t)s * 32 * D_DIM;
        #pragma unroll
        for (int i = 0; i < 4; i++) {
            int cb = bc0 + 16 * i;
            cp16(rb + bk * 1024 + ((cb ^ (bk & 7)) << 4), sB + cb * 4);
        }
    };

    // ---- ldmatrix address bases (per thread constants) ----
    const int mw = wid >> 2;          // 0..3  m-block of 32
    const int nw = wid & 3;           // 0..3  n-block of 64
    // A: lanes 0-7 m0-7/k0, 8-15 m8-15/k0, 16-23 m0-7/k8, 24-31 m8-15/k8
    const int a_m  = mw * 32 + (lane & 7) + ((lane >> 3) & 1) * 8;
    const int a_kb = ((lane >> 4) & 1) * 16;     // byte offset (k*2)
    // B: lanes 0-7 k0-7/n0, 8-15 k8-15/n0, 16-23 k0-7/n8, 24-31 k8-15/n8
    const int b_k0 = (lane & 7) + ((lane >> 3) & 1) * 8;
    const int b_nb = nw * 128 + ((lane >> 4) & 1) * 16;  // byte offset (n*2)

    const int gid = lane >> 2;
    const int tig = lane & 3;

    float acc[2][8][4];
    #pragma unroll
    for (int i = 0; i < 2; i++)
        #pragma unroll
        for (int j = 0; j < 8; j++)
            #pragma unroll
            for (int q = 0; q < 4; q++) acc[i][j][q] = 0.0f;

    // prologue: stages 0,1 in flight
    issue(0, 0); cp_commit();
    issue(1, 1); cp_commit();

    for (int s = 0; s < nsteps; s++) {
        const int buf = s & 1;
        cp_wait1();              // group s complete (s+1 still in flight)
        __syncthreads();

        // ---- convert raw fp32 -> f16 hi/lo tiles ----
        const char* rawA = smem + buf * RAW_STAGE;
        const char* rawB = rawA + RAWA_BYTES;
        char* fA = smem + SMEM_F16_BASE + buf * F16_STAGE;
        char* fB = fA + F16A_BYTES;

        // A: warp handles 8 m-rows
        #pragma unroll
        for (int i = 0; i < 2; i++) {
            const int m  = wid * 8 + i * 4 + (lane >> 3);
            const int cb = lane & 7;
            const int sx = (m & 7) << 4;
            float4 v = *(const float4*)(rawA + m * 128 + ((cb << 4) ^ sx));
            uint32_t h0, l0, h1, l1;
            hsplit2(v.x, v.y, h0, l0);
            hsplit2(v.z, v.w, h1, l1);
            *(uint2*)(fA + m * 128 + ((cb * 8) ^ sx))        = make_uint2(h0, h1);
            *(uint2*)(fA + m * 128 + ((64 + cb * 8) ^ sx))   = make_uint2(l0, l1);
        }
        // B: warp handles 2 k-rows
        #pragma unroll
        for (int r = 0; r < 2; r++) {
            const int k  = wid * 2 + r;
            const int sx = (k & 7) << 4;
            #pragma unroll
            for (int j = 0; j < 2; j++) {
                const int cb = lane + j * 32;
                float4 v = *(const float4*)(rawB + k * 1024 + ((cb << 4) ^ sx));
                uint32_t h0, l0, h1, l1;
                hsplit2(v.x, v.y, h0, l0);
                hsplit2(v.z, v.w, h1, l1);
                *(uint2*)(fB + k * 1024 + ((cb * 8) ^ sx))       = make_uint2(h0, h1);
                *(uint2*)(fB + k * 1024 + 512 + ((cb * 8) ^ sx)) = make_uint2(l0, l1);
            }
        }
        __syncthreads();         // raw[buf] free, f16[buf] visible

        if (s + 2 < nsteps) issue(s + 2, buf);
        cp_commit();             // always commit (possibly empty group)

        // ---- MMA over f16[buf]: 2 k16 x (2 mt x 8 nt) x 3 terms ----
        const uint32_t fAu = sb + SMEM_F16_BASE + buf * F16_STAGE;
        const uint32_t fBu = fAu + F16A_BYTES;
        // per-mt A address base (kk folds in via ^ (kk<<5))
        uint32_t aBase[2];
        #pragma unroll
        for (int mt = 0; mt < 2; mt++) {
            const int m = a_m + mt * 16;
            aBase[mt] = fAu + m * 128 + (a_kb ^ ((m & 7) << 4));
        }
        #pragma unroll
        for (int kk = 0; kk < 2; kk++) {
            uint32_t ahi[2][4], alo[2][4];
            #pragma unroll
            for (int mt = 0; mt < 2; mt++) {
                const uint32_t aa = aBase[mt] ^ (kk << 5);
                ldsm_x4(ahi[mt], aa);
                ldsm_x4(alo[mt], aa ^ 64);
            }
            const int kr = kk * 16 + b_k0;
            const uint32_t bBase = fBu + kr * 1024 + (b_nb ^ ((kr & 7) << 4));
            #pragma unroll
            for (int p = 0; p < 4; p++) {
                uint32_t bhi[4], blo[4];
                const uint32_t ba = bBase ^ (p << 5);
                ldsm_x4_t(bhi, ba);
                ldsm_x4_t(blo, ba + 512);
                #pragma unroll
                for (int mt = 0; mt < 2; mt++) {
                    #pragma unroll
                    for (int tt = 0; tt < 2; tt++) {
                        float* c = acc[mt][p * 2 + tt];
                        mma16816(c, ahi[mt], &bhi[2 * tt]);
                        mma16816(c, ahi[mt], &blo[2 * tt]);
                        mma16816(c, alo[mt], &bhi[2 * tt]);
                    }
                }
            }
        }
    }

    // ---- epilogue: write partial tile ----
    #pragma unroll
    for (int mt = 0; mt < 2; mt++) {
        const int r0 = mw * 32 + mt * 16 + gid;
        #pragma unroll
        for (int nt = 0; nt < 8; nt++) {
            const int col = ncol0 + nw * 64 + nt * 8 + tig * 2;
            float* base0 = g_partial + ((size_t)(kidx * M_ROWS + r0) << 9) + col;
            *(float2*)base0 = make_float2(acc[mt][nt][0], acc[mt][nt][1]);
            *(float2*)(base0 + (8 << 9)) = make_float2(acc[mt][nt][2], acc[mt][nt][3]);
        }
    }
}

// ---------------------------------------------------------------------------
// Kernel 2: reduce 74 partials + bias -> e[128][512]
// ---------------------------------------------------------------------------
__global__ __launch_bounds__(512)
void reduce_kernel(const float* __restrict__ b) {
    const int gid = blockIdx.x * 512 + threadIdx.x;   // 0 .. 65535
    float s = __ldg(b + (gid & 511));
    const float* p = g_partial + gid;
    #pragma unroll 2
    for (int k = 0; k < KSPLITS; k++)
        s += p[(size_t)k * (M_ROWS * D_DIM)];
    g_e[gid] = s;
}

// ---------------------------------------------------------------------------
// Kernel 3: d[i,j,0,g,c] = (e[j*4][c] - e[((i+j)%32)*4+1+g][c])^2
// ---------------------------------------------------------------------------
__global__ __launch_bounds__(512)
void dist_kernel(float* __restrict__ out) {
    const int bx = blockIdx.x;          // 0..3071 = i*96 + j*3 + g
    const int c  = threadIdx.x;
    const int g  = bx % 3;
    const int j  = (bx / 3) & 31;
    const int i  = bx / 96;
    const float ep = g_e[(j * 4) * D_DIM + c];
    const float eg = g_e[((((i + j) & 31) * 4) + g + 1) * D_DIM + c];
    const float df = ep - eg;
    out[(size_t)bx * D_DIM + c] = df * df;
}

// ---------------------------------------------------------------------------
// Kernel 4: w (32,32,3,3) and label (32,32,1,3) as 0/1 floats
// ---------------------------------------------------------------------------
__global__ __launch_bounds__(1024)
void wl_kernel(const int* __restrict__ y, float* __restrict__ out) {
    const int t = blockIdx.x * 1024 + threadIdx.x;   // 0 .. 12287
    if (t < W_ELEMS) {
        const int p = t % 3;
        const int a = (t / 3) % 3;
        const int j = (t / 9) & 31;
        const int i = t / 288;
        const int r = (i + j) & 31;
        out[W_OFF + t] = (y[j * 4 + 1 + a] == y[r * 4 + 1 + p]) ? 1.0f : 0.0f;
    } else if (t < W_ELEMS + L_ELEMS) {
        const int u = t - W_ELEMS;
        const int p = u % 3;
        const int j = (u / 3) & 31;
        const int i = u / 96;
        const int r = (i + j) & 31;
        out[L_OFF + u] = (y[j * 4] == y[r * 4 + 1 + p]) ? 1.0f : 0.0f;
    }
}

// ---------------------------------------------------------------------------
// Launch
// ---------------------------------------------------------------------------
extern "C" void kernel_launch(void* const* d_in, const int* in_sizes, int n_in,
                              void* d_out, int out_size) {
    const float* x = (const float*)d_in[0];
    const int*   y = (const int*)d_in[1];
    const float* W = (const float*)d_in[2];
    const float* b = (const float*)d_in[3];
    float* out = (float*)d_out;

    static bool attr_set = false;
    if (!attr_set) {
        cudaFuncSetAttribute(gemm_split_kernel,
                             cudaFuncAttributeMaxDynamicSharedMemorySize,
                             SMEM_TOTAL);
        attr_set = true;
    }

    gemm_split_kernel<<<KSPLITS * 2, 512, SMEM_TOTAL>>>(x, W);
    reduce_kernel<<<128, 512>>>(b);
    dist_kernel<<<3072, 512>>>(out);
    wl_kernel<<<12, 1024>>>(y, out);
}

// round 3
// speedup vs baseline: 1.2045x; 1.2045x over previous
#include <cuda_runtime.h>
#include <cstdint>

// ---------------------------------------------------------------------------
// Problem constants
// ---------------------------------------------------------------------------
#define K_TOTAL   98304      // F = 3*256*128
#define KSPLITS   74
#define M_ROWS    128        // B*N = 32*4
#define D_DIM     512
#define N_TILE    256        // N per CTA (2 halves)

#define D_ELEMS   (32*32*3*512)        // 1572864
#define W_ELEMS   (32*32*3*3)          // 9216
#define L_ELEMS   (32*32*3)            // 3072
#define W_OFF     D_ELEMS
#define L_OFF     (D_ELEMS + W_ELEMS)

// smem: raw fp32 triple-buffer + f16 double-buffer
#define RAWA_BYTES 16384     // 128 m x 32 k fp32
#define RAWB_BYTES 32768     // 32 k x 256 n fp32
#define RAW_STAGE  (RAWA_BYTES + RAWB_BYTES)       // 49152
#define F16A_BYTES 16384     // 128 rows x (32 hi + 32 lo) f16 = 128B rows
#define F16B_BYTES 16384     // 32 rows x 256 f16 hi = 512B rows
#define F16_STAGE  (F16A_BYTES + F16B_BYTES)       // 32768
#define SMEM_F16_BASE (3 * RAW_STAGE)              // 147456
#define SMEM_TOTAL (3 * RAW_STAGE + 2 * F16_STAGE) // 212992 (208KB)

// ---------------------------------------------------------------------------
// Scratch (static __device__: no allocation allowed)
// ---------------------------------------------------------------------------
__device__ float g_partial[(size_t)KSPLITS * M_ROWS * D_DIM];   // ~18.5 MB
__device__ float g_e[M_ROWS * D_DIM];                           // 256 KB

// ---------------------------------------------------------------------------
// PTX helpers (sm_80-era: portable to sm_100 base target)
// ---------------------------------------------------------------------------
__device__ __forceinline__ uint32_t smem_u32(const void* p) {
    uint32_t a;
    asm("{ .reg .u64 t; cvta.to.shared.u64 t, %1; cvt.u32.u64 %0, t; }"
        : "=r"(a) : "l"(p));
    return a;
}

__device__ __forceinline__ void cp16(uint32_t dst, const void* src) {
    asm volatile("cp.async.cg.shared.global [%0], [%1], 16;"
                 :: "r"(dst), "l"(src) : "memory");
}
__device__ __forceinline__ void cp_commit() {
    asm volatile("cp.async.commit_group;" ::: "memory");
}
__device__ __forceinline__ void cp_wait2() {
    asm volatile("cp.async.wait_group 2;" ::: "memory");
}

__device__ __forceinline__ void ldsm_x4(uint32_t* r, uint32_t a) {
    asm volatile("ldmatrix.sync.aligned.m8n8.x4.shared.b16 {%0,%1,%2,%3}, [%4];"
                 : "=r"(r[0]), "=r"(r[1]), "=r"(r[2]), "=r"(r[3]) : "r"(a));
}
__device__ __forceinline__ void ldsm_x4_t(uint32_t* r, uint32_t a) {
    asm volatile("ldmatrix.sync.aligned.m8n8.x4.trans.shared.b16 {%0,%1,%2,%3}, [%4];"
                 : "=r"(r[0]), "=r"(r[1]), "=r"(r[2]), "=r"(r[3]) : "r"(a));
}

__device__ __forceinline__ void mma16816(float* c, const uint32_t* a,
                                         const uint32_t* b) {
    asm volatile(
        "mma.sync.aligned.m16n8k16.row.col.f32.f16.f16.f32 "
        "{%0,%1,%2,%3}, {%4,%5,%6,%7}, {%8,%9}, {%0,%1,%2,%3};"
        : "+f"(c[0]), "+f"(c[1]), "+f"(c[2]), "+f"(c[3])
        : "r"(a[0]), "r"(a[1]), "r"(a[2]), "r"(a[3]), "r"(b[0]), "r"(b[1]));
}

// fp32 pair -> f16x2 hi + f16x2 lo (residual)
__device__ __forceinline__ void hsplit2(float f0, float f1,
                                        uint32_t& hi, uint32_t& lo) {
    uint32_t h;
    asm("cvt.rn.f16x2.f32 %0, %1, %2;" : "=r"(h) : "f"(f1), "f"(f0));
    float h0, h1;
    asm("{.reg .f16 x,y; mov.b32 {x,y}, %2; cvt.f32.f16 %0, x; cvt.f32.f16 %1, y;}"
        : "=f"(h0), "=f"(h1) : "r"(h));
    float r0 = f0 - h0;
    float r1 = f1 - h1;
    asm("cvt.rn.f16x2.f32 %0, %1, %2;" : "=r"(lo) : "f"(r1), "f"(r0));
    hi = h;
}

// ---------------------------------------------------------------------------
// Kernel 1: split-K 2-term fp16 GEMM (A = hi+lo, B = hi) -> partial sums
// grid = 148 CTAs: blockIdx.x = kidx*2 + nhalf ; 512 threads
// ---------------------------------------------------------------------------
__global__ __launch_bounds__(512, 1)
void gemm_split_kernel(const float* __restrict__ x, const float* __restrict__ W) {
    extern __shared__ char smem[];
    const uint32_t sb = smem_u32(smem);
    const int tid  = threadIdx.x;
    const int wid  = tid >> 5;
    const int lane = tid & 31;

    const int nhalf = blockIdx.x & 1;
    const int kidx  = blockIdx.x >> 1;
    const int ncol0 = nhalf * N_TILE;
    // distribute 3072 32-wide K-steps over 74 splits: 38 CTAs get 42, rest 41
    const int nsteps = 41 + (kidx < 38 ? 1 : 0);
    const int step0  = kidx * 41 + (kidx < 38 ? kidx : 38);

    // ---- cp.async issue mapping ----
    const int am  = tid & 127;
    const int ac0 = (tid >> 7) * 2;
    const int bk  = tid >> 4;
    const int bc0 = tid & 15;
    const float* srcA0 = x + (size_t)am * K_TOTAL + (size_t)step0 * 32;
    const float* srcB0 = W + ((size_t)step0 * 32 + bk) * D_DIM + ncol0;

    auto issue = [&](int s, int rbuf) {
        const uint32_t ra = sb + rbuf * RAW_STAGE;
        const uint32_t rb = ra + RAWA_BYTES;
        const float* sA = srcA0 + (size_t)s * 32;
        #pragma unroll
        for (int i = 0; i < 2; i++) {
            int cb = ac0 + i;
            cp16(ra + am * 128 + ((cb ^ (am & 7)) << 4), sA + cb * 4);
        }
        const float* sB = srcB0 + (size_t)s * 32 * D_DIM;
        #pragma unroll
        for (int i = 0; i < 4; i++) {
            int cb = bc0 + 16 * i;
            cp16(rb + bk * 1024 + ((cb ^ (bk & 7)) << 4), sB + cb * 4);
        }
    };

    // ---- ldmatrix address constants ----
    const int mw = wid >> 2;          // 0..3  m-block of 32
    const int nw = wid & 3;           // 0..3  n-block of 64
    const int a_m  = mw * 32 + (lane & 7) + ((lane >> 3) & 1) * 8;
    const int a_kb = ((lane >> 4) & 1) * 16;
    const int b_k0 = (lane & 7) + ((lane >> 3) & 1) * 8;
    const int b_nb = nw * 128 + ((lane >> 4) & 1) * 16;

    const int gid = lane >> 2;
    const int tig = lane & 3;

    float acc[2][8][4];
    #pragma unroll
    for (int i = 0; i < 2; i++)
        #pragma unroll
        for (int j = 0; j < 8; j++)
            #pragma unroll
            for (int q = 0; q < 4; q++) acc[i][j][q] = 0.0f;

    // prologue: 3 raw stages in flight
    issue(0, 0); cp_commit();
    issue(1, 1); cp_commit();
    issue(2, 2); cp_commit();

    int rbuf = 0;   // s % 3
    for (int s = 0; s < nsteps; s++) {
        const int fbuf = s & 1;
        cp_wait2();              // group s complete (s+1, s+2 in flight)
        __syncthreads();

        // ---- convert raw fp32 -> f16 tiles ----
        const char* rawA = smem + rbuf * RAW_STAGE;
        const char* rawB = rawA + RAWA_BYTES;
        char* fA = smem + SMEM_F16_BASE + fbuf * F16_STAGE;
        char* fB = fA + F16A_BYTES;

        // A: warp handles 8 m-rows, split hi/lo
        #pragma unroll
        for (int i = 0; i < 2; i++) {
            const int m  = wid * 8 + i * 4 + (lane >> 3);
            const int cb = lane & 7;
            const int sx = (m & 7) << 4;
            float4 v = *(const float4*)(rawA + m * 128 + ((cb << 4) ^ sx));
            uint32_t h0, l0, h1, l1;
            hsplit2(v.x, v.y, h0, l0);
            hsplit2(v.z, v.w, h1, l1);
            *(uint2*)(fA + m * 128 + ((cb * 8) ^ sx))      = make_uint2(h0, h1);
            *(uint2*)(fA + m * 128 + ((64 + cb * 8) ^ sx)) = make_uint2(l0, l1);
        }
        // B: warp handles 2 k-rows, hi only
        #pragma unroll
        for (int r = 0; r < 2; r++) {
            const int k  = wid * 2 + r;
            const int sx = (k & 7) << 4;
            #pragma unroll
            for (int j = 0; j < 2; j++) {
                const int cb = lane + j * 32;
                float4 v = *(const float4*)(rawB + k * 1024 + ((cb << 4) ^ sx));
                uint32_t h01, h23;
                asm("cvt.rn.f16x2.f32 %0, %1, %2;" : "=r"(h01) : "f"(v.y), "f"(v.x));
                asm("cvt.rn.f16x2.f32 %0, %1, %2;" : "=r"(h23) : "f"(v.w), "f"(v.z));
                *(uint2*)(fB + k * 512 + ((cb * 8) ^ sx)) = make_uint2(h01, h23);
            }
        }
        __syncthreads();         // raw[rbuf] free, f16[fbuf] visible

        if (s + 3 < nsteps) issue(s + 3, rbuf);
        cp_commit();             // always commit (possibly empty group)
        rbuf = (rbuf == 2) ? 0 : rbuf + 1;

        // ---- MMA over f16[fbuf]: 2 kk x 4 p x (2 mt x 2 tt) x 2 terms ----
        const uint32_t fAu = sb + SMEM_F16_BASE + fbuf * F16_STAGE;
        const uint32_t fBu = fAu + F16A_BYTES;
        uint32_t aBase[2];
        #pragma unroll
        for (int mt = 0; mt < 2; mt++) {
            const int m = a_m + mt * 16;
            aBase[mt] = fAu + m * 128 + (a_kb ^ ((m & 7) << 4));
        }
        #pragma unroll
        for (int kk = 0; kk < 2; kk++) {
            uint32_t ahi[2][4], alo[2][4];
            #pragma unroll
            for (int mt = 0; mt < 2; mt++) {
                const uint32_t aa = aBase[mt] ^ (kk << 5);
                ldsm_x4(ahi[mt], aa);
                ldsm_x4(alo[mt], aa ^ 64);
            }
            const int kr = kk * 16 + b_k0;
            const uint32_t bBase = fBu + kr * 512 + (b_nb ^ ((kr & 7) << 4));
            #pragma unroll
            for (int p = 0; p < 4; p++) {
                uint32_t bhi[4];
                ldsm_x4_t(bhi, bBase ^ (p << 5));
                #pragma unroll
                for (int mt = 0; mt < 2; mt++) {
                    #pragma unroll
                    for (int tt = 0; tt < 2; tt++) {
                        float* c = acc[mt][p * 2 + tt];
                        mma16816(c, ahi[mt], &bhi[2 * tt]);
                        mma16816(c, alo[mt], &bhi[2 * tt]);
                    }
                }
            }
        }
    }

    // ---- epilogue: write partial tile ----
    #pragma unroll
    for (int mt = 0; mt < 2; mt++) {
        const int r0 = mw * 32 + mt * 16 + gid;
        #pragma unroll
        for (int nt = 0; nt < 8; nt++) {
            const int col = ncol0 + nw * 64 + nt * 8 + tig * 2;
            float* base0 = g_partial + ((size_t)(kidx * M_ROWS + r0) << 9) + col;
            *(float2*)base0 = make_float2(acc[mt][nt][0], acc[mt][nt][1]);
            *(float2*)(base0 + (8 << 9)) = make_float2(acc[mt][nt][2], acc[mt][nt][3]);
        }
    }
}

// ---------------------------------------------------------------------------
// Kernel 2: reduce 74 partials + bias -> e[128][512]
// ---------------------------------------------------------------------------
__global__ __launch_bounds__(512)
void reduce_kernel(const float* __restrict__ b) {
    const int gid = blockIdx.x * 512 + threadIdx.x;   // 0 .. 65535
    float s = __ldg(b + (gid & 511));
    const float* p = g_partial + gid;
    #pragma unroll 2
    for (int k = 0; k < KSPLITS; k++)
        s += p[(size_t)k * (M_ROWS * D_DIM)];
    g_e[gid] = s;
}

// ---------------------------------------------------------------------------
// Kernel 3: d[i,j,0,g,c] = (e[j*4][c] - e[((i+j)%32)*4+1+g][c])^2
// ---------------------------------------------------------------------------
__global__ __launch_bounds__(512)
void dist_kernel(float* __restrict__ out) {
    const int bx = blockIdx.x;          // 0..3071 = i*96 + j*3 + g
    const int c  = threadIdx.x;
    const int g  = bx % 3;
    const int j  = (bx / 3) & 31;
    const int i  = bx / 96;
    const float ep = g_e[(j * 4) * D_DIM + c];
    const float eg = g_e[((((i + j) & 31) * 4) + g + 1) * D_DIM + c];
    const float df = ep - eg;
    out[(size_t)bx * D_DIM + c] = df * df;
}

// ---------------------------------------------------------------------------
// Kernel 4: w (32,32,3,3) and label (32,32,1,3) as 0/1 floats
// ---------------------------------------------------------------------------
__global__ __launch_bounds__(1024)
void wl_kernel(const int* __restrict__ y, float* __restrict__ out) {
    const int t = blockIdx.x * 1024 + threadIdx.x;   // 0 .. 12287
    if (t < W_ELEMS) {
        const int p = t % 3;
        const int a = (t / 3) % 3;
        const int j = (t / 9) & 31;
        const int i = t / 288;
        const int r = (i + j) & 31;
        out[W_OFF + t] = (y[j * 4 + 1 + a] == y[r * 4 + 1 + p]) ? 1.0f : 0.0f;
    } else if (t < W_ELEMS + L_ELEMS) {
        const int u = t - W_ELEMS;
        const int p = u % 3;
        const int j = (u / 3) & 31;
        const int i = u / 96;
        const int r = (i + j) & 31;
        out[L_OFF + u] = (y[j * 4] == y[r * 4 + 1 + p]) ? 1.0f : 0.0f;
    }
}

// ---------------------------------------------------------------------------
// Launch
// ---------------------------------------------------------------------------
extern "C" void kernel_launch(void* const* d_in, const int* in_sizes, int n_in,
                              void* d_out, int out_size) {
    const float* x = (const float*)d_in[0];
    const int*   y = (const int*)d_in[1];
    const float* W = (const float*)d_in[2];
    const float* b = (const float*)d_in[3];
    float* out = (float*)d_out;

    static bool attr_set = false;
    if (!attr_set) {
        cudaFuncSetAttribute(gemm_split_kernel,
                             cudaFuncAttributeMaxDynamicSharedMemorySize,
                             SMEM_TOTAL);
        attr_set = true;
    }

    gemm_split_kernel<<<KSPLITS * 2, 512, SMEM_TOTAL>>>(x, W);
    reduce_kernel<<<128, 512>>>(b);
    dist_kernel<<<3072, 512>>>(out);
    wl_kernel<<<12, 1024>>>(y, out);
}